// round 11
// baseline (speedup 1.0000x reference)
#include <cuda_runtime.h>
#include <cuda_bf16.h>
#include <cstdint>

// Problem constants
#define NB      16
#define CDIM    64
#define HWDIM   4096
#define NTOT    65536
#define KCB     512
#define OUT_Q   4194304
#define OFF_LOSS (OUT_Q)
#define OFF_PERP (OUT_Q + 1)
#define OFF_ACT  (OUT_Q + 2)
#define OFF_IDX  (OUT_Q + 3)

#define TPB     512
#define GRID    148
#define TILEP   64
#define NTILES  (NTOT / TILEP)      // 1024 -> 6.92/CTA -> 0.988 balance

// smem rows padded to 72 halves (144B = 36 banks) -> ldmatrix conflict-free
#define ROWB    144
// ---- dynamic smem byte offsets ----
#define SO_BHI   0                  // E_hi bf16 [512][72h]  = 73728
#define SO_BLO   73728              // E_lo                  = 73728
#define SO_AHI   147456             // X_hi bf16 [64][72h]   =  9216
#define SO_ALO   156672             // X_lo                  =  9216
#define SO_XF    165888             // X fp32 [64][68]       = 17408
#define SO_SNORM 183296             // 512 f
#define SO_H     185344             // 512 f (= norm/2)
#define SO_SD    187392             // float [64][4][2]      =  2048
#define SO_SI    189440             // int   [64][4][2]      =  2048
#define SO_HIST  191488             // 512 u32
#define SO_SBK   193536             // 64 int
#define SO_WSUM  193792             // 16 f
#define SO_RD    193856             // float [3][64] rescored dists = 768
#define SO_RK    194624             // int   [3][64] rescored ks    = 768
#define SMEM_BYTES 195392

__device__ float        g_loss;
__device__ unsigned int g_hist[KCB];

// ---------------- family-portable tensor helpers (sm_80+ PTX only) --------
__device__ __forceinline__ void mma16816(float* d, const uint32_t* a,
                                         const uint32_t* b) {
    asm volatile(
        "mma.sync.aligned.m16n8k16.row.col.f32.bf16.bf16.f32 "
        "{%0,%1,%2,%3}, {%4,%5,%6,%7}, {%8,%9}, {%0,%1,%2,%3};"
        : "+f"(d[0]), "+f"(d[1]), "+f"(d[2]), "+f"(d[3])
        : "r"(a[0]), "r"(a[1]), "r"(a[2]), "r"(a[3]), "r"(b[0]), "r"(b[1]));
}
__device__ __forceinline__ void ldsm4(uint32_t* r, uint32_t addr) {
    asm volatile("ldmatrix.sync.aligned.m8n8.x4.shared.b16 {%0,%1,%2,%3}, [%4];"
                 : "=r"(r[0]), "=r"(r[1]), "=r"(r[2]), "=r"(r[3]) : "r"(addr));
}
__device__ __forceinline__ void pack_hilo(float f0, float f1,
                                          uint32_t& whi, uint32_t& wlo) {
    __nv_bfloat16 h0 = __float2bfloat16_rn(f0);
    __nv_bfloat16 h1 = __float2bfloat16_rn(f1);
    float r0 = f0 - __bfloat162float(h0);
    float r1 = f1 - __bfloat162float(h1);
    __nv_bfloat16 l0 = __float2bfloat16_rn(r0);
    __nv_bfloat16 l1 = __float2bfloat16_rn(r1);
    whi = (uint32_t)__bfloat16_as_ushort(h0) | ((uint32_t)__bfloat16_as_ushort(h1) << 16);
    wlo = (uint32_t)__bfloat16_as_ushort(l0) | ((uint32_t)__bfloat16_as_ushort(l1) << 16);
}
__device__ __forceinline__ void top2_upd(float m, int k,
                                         float& b1, float& b2, int& k1, int& k2) {
    if (m > b2) {
        if (m > b1) { b2 = b1; k2 = k1; b1 = m; k1 = k; }
        else        { b2 = m;  k2 = k; }
    }
}
__device__ __forceinline__ void top3_upd(float m, int k,
                                         float& b1, float& b2, float& b3,
                                         int& k1, int& k2, int& k3) {
    if (m > b3) {
        if (m > b2) {
            b3 = b2; k3 = k2;
            if (m > b1) { b2 = b1; k2 = k1; b1 = m; k1 = k; }
            else        { b2 = m;  k2 = k; }
        } else { b3 = m; k3 = k; }
    }
}

// ---------------------------------------------------------------------------
extern __shared__ char sm[];

__global__ __launch_bounds__(TPB, 1)
void vq_main(const float* __restrict__ x,
             const float* __restrict__ E,
             float* __restrict__ out) {
    float*        sxf   = (float*)(sm + SO_XF);
    float*        snorm = (float*)(sm + SO_SNORM);
    float*        hh    = (float*)(sm + SO_H);
    float*        sd    = (float*)(sm + SO_SD);
    int*          si    = (int*)(sm + SO_SI);
    unsigned int* shist = (unsigned int*)(sm + SO_HIST);
    int*          sbk   = (int*)(sm + SO_SBK);
    float*        wsum  = (float*)(sm + SO_WSUM);
    float*        rd    = (float*)(sm + SO_RD);
    int*          rk    = (int*)(sm + SO_RK);

    const int tid  = threadIdx.x;
    const int wid  = tid >> 5;
    const int lane = tid & 31;

    // ---- one-time: codebook -> bf16 hi/lo (padded rows) + norms
    {
        const int k = tid;
        const float4* er = reinterpret_cast<const float4*>(E + (k << 6));
        char* bh = sm + SO_BHI + k * ROWB;
        char* bl = sm + SO_BLO + k * ROWB;
        float s = 0.f;
#pragma unroll
        for (int i = 0; i < 16; i++) {
            float4 v = er[i];
            s = fmaf(v.x, v.x, s); s = fmaf(v.y, v.y, s);
            s = fmaf(v.z, v.z, s); s = fmaf(v.w, v.w, s);
            uint32_t whi, wlo;
            pack_hilo(v.x, v.y, whi, wlo);
            *(uint32_t*)(bh + i * 8)     = whi;
            *(uint32_t*)(bl + i * 8)     = wlo;
            pack_hilo(v.z, v.w, whi, wlo);
            *(uint32_t*)(bh + i * 8 + 4) = whi;
            *(uint32_t*)(bl + i * 8 + 4) = wlo;
        }
        snorm[k] = s;
        hh[k]    = 0.5f * s;
        shist[k] = 0u;
    }
    __syncthreads();

    const int pw  = tid & 63;     // staging point
    const int cgi = tid >> 6;     // staging channel group (0..7)
    const int rg  = wid >> 2;     // row group: points rg*16 .. +15
    const int wq  = wid & 3;      // code quarter: codes wq*128 .. +127

    // ldmatrix lane addressing
    const uint32_t smu = (uint32_t)__cvta_generic_to_shared(sm);
    const int sel = lane >> 3;
    const uint32_t aoff =
        (uint32_t)(rg * 16 + (lane & 7) + (sel & 1) * 8) * ROWB + (uint32_t)((sel >> 1) * 16);
    const uint32_t ahiA = smu + SO_AHI + aoff;
    const uint32_t aloA = smu + SO_ALO + aoff;
    const uint32_t bln  = (uint32_t)((lane & 7) * ROWB + (lane >> 3) * 16);
    const uint32_t bhiB = smu + SO_BHI + bln;
    const uint32_t bloB = smu + SO_BLO + bln;

    float loss_acc = 0.f, xsq_acc = 0.f;

    for (int t = blockIdx.x; t < NTILES; t += GRID) {
        const int nb  = t << 6;
        const int b   = nb >> 12;
        const int hwb = nb & (HWDIM - 1);
        const float* xg = x + (size_t)b * CDIM * HWDIM + hwb;

        // ---- stage X tile: bf16 hi/lo (MMA) + fp32 (rescore)
#pragma unroll
        for (int jj = 0; jj < 4; jj++) {
            int c0 = (cgi << 3) + (jj << 1);
            float v0 = xg[(size_t)c0 * HWDIM + pw];
            float v1 = xg[(size_t)(c0 + 1) * HWDIM + pw];
            xsq_acc = fmaf(v0, v0, xsq_acc);
            xsq_acc = fmaf(v1, v1, xsq_acc);
            uint32_t whi, wlo;
            pack_hilo(v0, v1, whi, wlo);
            *(uint32_t*)(sm + SO_AHI + pw * ROWB + c0 * 2) = whi;
            *(uint32_t*)(sm + SO_ALO + pw * ROWB + c0 * 2) = wlo;
            sxf[pw * 68 + c0]     = v0;
            sxf[pw * 68 + c0 + 1] = v1;
        }
        __syncthreads();

        // ---- A fragments (persist across the n-loop)
        uint32_t ahi[16], alo[16];
#pragma unroll
        for (int kt = 0; kt < 4; kt++) {
            ldsm4(ahi + 4 * kt, ahiA + kt * 32);
            ldsm4(alo + 4 * kt, aloA + kt * 32);
        }

        // ---- per-lane top-2 of m = dot - ||e||^2/2 (h folded into acc init)
        float a1 = -3.4e38f, a2 = -3.4e38f;      // row rg*16 + (lane>>2)
        float c1 = -3.4e38f, c2 = -3.4e38f;      // row +8
        int ka1 = 0, ka2 = 0, kc1 = 0, kc2 = 0;

        const uint32_t nqbase = (uint32_t)(wq * 128) * ROWB;
#pragma unroll 2
        for (int nt = 0; nt < 16; nt++) {
            const uint32_t nbyt = nqbase + (uint32_t)(nt * 8) * ROWB;
            const int c0 = wq * 128 + nt * 8 + 2 * (lane & 3);
            float2 hp = *(const float2*)(hh + c0);
            float acc1[4] = {-hp.x, -hp.y, -hp.x, -hp.y};   // h folded in
            float acc2[4] = {0.f, 0.f, 0.f, 0.f};
            uint32_t bh[8], bl[8];
            ldsm4(bh,     bhiB + nbyt);
            ldsm4(bh + 4, bhiB + nbyt + 64);
            ldsm4(bl,     bloB + nbyt);
            ldsm4(bl + 4, bloB + nbyt + 64);
#pragma unroll
            for (int kt = 0; kt < 4; kt++) {
                mma16816(acc1, ahi + 4 * kt, bh + 2 * kt);  // hi*hi
                mma16816(acc2, alo + 4 * kt, bh + 2 * kt);  // lo*hi
                mma16816(acc1, ahi + 4 * kt, bl + 2 * kt);  // hi*lo
            }
            top2_upd(acc1[0] + acc2[0], c0,     a1, a2, ka1, ka2);
            top2_upd(acc1[1] + acc2[1], c0 + 1, a1, a2, ka1, ka2);
            top2_upd(acc1[2] + acc2[2], c0,     c1, c2, kc1, kc2);
            top2_upd(acc1[3] + acc2[3], c0 + 1, c1, c2, kc1, kc2);
        }

        // ---- merge across the 4 lanes sharing each row (bfly 1,2)
#pragma unroll
        for (int off = 1; off <= 2; off <<= 1) {
            float o1 = __shfl_xor_sync(0xFFFFFFFFu, a1, off);
            float o2 = __shfl_xor_sync(0xFFFFFFFFu, a2, off);
            int   p1 = __shfl_xor_sync(0xFFFFFFFFu, ka1, off);
            int   p2 = __shfl_xor_sync(0xFFFFFFFFu, ka2, off);
            top2_upd(o1, p1, a1, a2, ka1, ka2);
            top2_upd(o2, p2, a1, a2, ka1, ka2);
            o1 = __shfl_xor_sync(0xFFFFFFFFu, c1, off);
            o2 = __shfl_xor_sync(0xFFFFFFFFu, c2, off);
            p1 = __shfl_xor_sync(0xFFFFFFFFu, kc1, off);
            p2 = __shfl_xor_sync(0xFFFFFFFFu, kc2, off);
            top2_upd(o1, p1, c1, c2, kc1, kc2);
            top2_upd(o2, p2, c1, c2, kc1, kc2);
        }
        if ((lane & 3) == 0) {
            int ra = rg * 16 + (lane >> 2);
            int rb = ra + 8;
            int ba = (ra * 4 + wq) * 2;
            int bb = (rb * 4 + wq) * 2;
            sd[ba] = a1; sd[ba + 1] = a2;
            si[ba] = ka1; si[ba + 1] = ka2;
            sd[bb] = c1; sd[bb + 1] = c2;
            si[bb] = kc1; si[bb + 1] = kc2;
        }
        __syncthreads();

        // ---- distributed exact rescore: thread (p, r) with r = tid>>6 < 3.
        //      Each redundantly re-derives the deterministic top-3 ranking
        //      (identical inputs/ops in all threads), takes its rank, and
        //      computes the EXACT fp32 distance (R1 formula/order).
        if (tid < 192) {
            const int p = tid & 63;
            const int r = tid >> 6;
            float m1 = -3.4e38f, m2 = -3.4e38f, m3 = -3.4e38f;
            int   i1 = 0, i2 = 0, i3 = 0;
#pragma unroll
            for (int qq = 0; qq < 4; qq++) {
                int bidx = (p * 4 + qq) * 2;
                top3_upd(sd[bidx],     si[bidx],     m1, m2, m3, i1, i2, i3);
                top3_upd(sd[bidx + 1], si[bidx + 1], m1, m2, m3, i1, i2, i3);
            }
            const int k = (r == 0) ? i1 : (r == 1) ? i2 : i3;
            const float4* xr4 = reinterpret_cast<const float4*>(sxf + p * 68);
            const float4* er  = reinterpret_cast<const float4*>(E + (k << 6));
            float q0 = 0.f, q1 = 0.f, q2 = 0.f, q3 = 0.f;
#pragma unroll
            for (int i = 0; i < 16; i++) {
                float4 xv = xr4[i];
                float4 ev = er[i];
                q0 = fmaf(xv.x, ev.x, q0);
                q1 = fmaf(xv.y, ev.y, q1);
                q2 = fmaf(xv.z, ev.z, q2);
                q3 = fmaf(xv.w, ev.w, q3);
            }
            float dot = (q0 + q1) + (q2 + q3);
            rd[(r << 6) + p] = fmaf(-2.f, dot, snorm[k]);
            rk[(r << 6) + p] = k;
        }
        __syncthreads();

        // ---- final pick (same r-order + tie rule as before)
        if (tid < TILEP) {
            float bd = 3.4e38f;
            int   bk = 1 << 30;
#pragma unroll
            for (int r = 0; r < 3; r++) {
                float d = rd[(r << 6) + tid];
                int   k = rk[(r << 6) + tid];
                if (d < bd || (d == bd && k < bk)) { bd = d; bk = k; }
            }
            loss_acc += bd;                       // + Σx² added globally
            sbk[tid] = bk;
            atomicAdd(&shist[bk], 1u);
            out[OFF_IDX + nb + tid] = (float)bk;
        }
        __syncthreads();

        // ---- vectorized writeout: thread (c, 4-point group) -> STG.128
        //      E reads coalesce across the 64 c-lanes per code row.
        {
            const int c  = tid & 63;
            const int gg = tid >> 6;              // 0..7
            float* op = out + (size_t)b * CDIM * HWDIM + hwb;
#pragma unroll
            for (int it = 0; it < 2; it++) {
                int g  = gg + (it << 3);          // 0..15
                int p0 = g << 2;
                int k0 = sbk[p0], k1 = sbk[p0 + 1], k2 = sbk[p0 + 2], k3 = sbk[p0 + 3];
                float4 v;
                v.x = E[(k0 << 6) + c];
                v.y = E[(k1 << 6) + c];
                v.z = E[(k2 << 6) + c];
                v.w = E[(k3 << 6) + c];
                *reinterpret_cast<float4*>(op + (size_t)c * HWDIM + p0) = v;
            }
        }
    }

    // ---- block reductions -> globals
    float tot = loss_acc + xsq_acc;
#pragma unroll
    for (int off = 16; off; off >>= 1)
        tot += __shfl_xor_sync(0xFFFFFFFFu, tot, off);
    if (lane == 0) wsum[wid] = tot;
    __syncthreads();

    atomicAdd(&g_hist[tid], shist[tid]);
    if (tid == 0) {
        float bsum = 0.f;
#pragma unroll
        for (int i = 0; i < 16; i++) bsum += wsum[i];
        atomicAdd(&g_loss, bsum);
    }
}

// ---------------------------------------------------------------------------
// finalize: perplexity + loss + active_codes; re-zero accumulators for the
// next graph replay.
// ---------------------------------------------------------------------------
__global__ void vq_finalize(const float* __restrict__ w, float* __restrict__ out) {
    __shared__ float s_ent[16];
    __shared__ float s_act[16];
    int t = threadIdx.x;

    float pr  = (float)g_hist[t] * (1.0f / (float)NTOT);
    float ent = pr * logf(pr + 1e-10f);
    float act = (w[t] >= 0.01f) ? 1.f : 0.f;

#pragma unroll
    for (int off = 16; off; off >>= 1) {
        ent += __shfl_xor_sync(0xFFFFFFFFu, ent, off);
        act += __shfl_xor_sync(0xFFFFFFFFu, act, off);
    }
    if ((t & 31) == 0) { s_ent[t >> 5] = ent; s_act[t >> 5] = act; }
    __syncthreads();
    if (t == 0) {
        float esum = 0.f, asum = 0.f;
#pragma unroll
        for (int i = 0; i < 16; i++) { esum += s_ent[i]; asum += s_act[i]; }
        out[OFF_LOSS] = g_loss * (1.0f / ((float)NTOT * (float)CDIM));
        out[OFF_PERP] = expf(-esum);
        out[OFF_ACT]  = asum;
    }
    __syncthreads();
    g_hist[t] = 0u;
    if (t == 0) g_loss = 0.f;
}

// ---------------------------------------------------------------------------
extern "C" void kernel_launch(void* const* d_in, const int* in_sizes, int n_in,
                              void* d_out, int out_size) {
    const float* x = (const float*)d_in[0];   // [16,64,64,64]
    const float* E = (const float*)d_in[1];   // [512,64]
    const float* w = (const float*)d_in[2];   // [512]
    float* out = (float*)d_out;

    cudaFuncSetAttribute(vq_main, cudaFuncAttributeMaxDynamicSharedMemorySize,
                         SMEM_BYTES);

    vq_main<<<GRID, TPB, SMEM_BYTES>>>(x, E, out);
    vq_finalize<<<1, KCB>>>(w, out);
}